// round 5
// baseline (speedup 1.0000x reference)
#include <cuda_runtime.h>
#include <cuda_bf16.h>
#include <cstdint>

// ======================= problem constants =======================
#define NB   3
#define BSZ  256
#define NF   8192
#define DDIM 2048
#define TEMP_INV 20.0f
#define NEPS 1e-12f

// GEMM tiling
#define BM 256
#define BN 64
#define BK 64
#define NK (DDIM / BK)          // 32
#define A_STAGE_BYTES (BM * BK * 2)   // 32768
#define B_STAGE_BYTES (BN * BK * 2)   // 8192
#define SMEM_DYN (3 * A_STAGE_BYTES + 2 * B_STAGE_BYTES)  // 114688

// ======================= static device scratch =======================
__device__ __align__(256) __nv_bfloat16 g_xn[NB * BSZ * DDIM];
__device__ float g_x2[NB * BSZ];
__device__ float g_sums[NB * BSZ * 4];   // per row: S1, E1(=S2), E2, E3
__device__ float g_rowloss[NB * BSZ];

// ======================= helpers =======================
__device__ __forceinline__ uint32_t smem_u32(const void* p) {
    uint32_t a;
    asm("{ .reg .u64 t; cvta.to.shared.u64 t, %1; cvt.u32.u64 %0, t; }" : "=r"(a) : "l"(p));
    return a;
}

__device__ __forceinline__ void cp16(uint32_t saddr, const void* g) {
    asm volatile("cp.async.cg.shared.global [%0], [%1], 16;" :: "r"(saddr), "l"(g) : "memory");
}
#define CP_COMMIT() asm volatile("cp.async.commit_group;" ::: "memory")
#define CP_WAIT0()  asm volatile("cp.async.wait_group 0;" ::: "memory")
#define CP_WAIT1()  asm volatile("cp.async.wait_group 1;" ::: "memory")

__device__ __forceinline__ void ldsm_x4(uint32_t* r, uint32_t addr) {
    asm volatile("ldmatrix.sync.aligned.m8n8.x4.shared.b16 {%0,%1,%2,%3}, [%4];"
                 : "=r"(r[0]), "=r"(r[1]), "=r"(r[2]), "=r"(r[3]) : "r"(addr));
}

__device__ __forceinline__ void mma16816(float* c, const uint32_t* a, uint32_t b0, uint32_t b1) {
    asm volatile(
        "mma.sync.aligned.m16n8k16.row.col.f32.bf16.bf16.f32 "
        "{%0,%1,%2,%3}, {%4,%5,%6,%7}, {%8,%9}, {%0,%1,%2,%3};"
        : "+f"(c[0]), "+f"(c[1]), "+f"(c[2]), "+f"(c[3])
        : "r"(a[0]), "r"(a[1]), "r"(a[2]), "r"(a[3]), "r"(b0), "r"(b1));
}

__device__ __forceinline__ void sts128u(uint32_t addr, uint32_t x, uint32_t y, uint32_t z, uint32_t w) {
    asm volatile("st.shared.v4.b32 [%0], {%1, %2, %3, %4};"
                 :: "r"(addr), "r"(x), "r"(y), "r"(z), "r"(w) : "memory");
}

__device__ __forceinline__ float blockReduceSum(float v) {
    __shared__ float red[8];
    const unsigned m = 0xffffffffu;
    v += __shfl_xor_sync(m, v, 16);
    v += __shfl_xor_sync(m, v, 8);
    v += __shfl_xor_sync(m, v, 4);
    v += __shfl_xor_sync(m, v, 2);
    v += __shfl_xor_sync(m, v, 1);
    __syncthreads();
    if ((threadIdx.x & 31) == 0) red[threadIdx.x >> 5] = v;
    __syncthreads();
    if (threadIdx.x < 8) {
        v = red[threadIdx.x];
        v += __shfl_xor_sync(0xffu, v, 4);
        v += __shfl_xor_sync(0xffu, v, 2);
        v += __shfl_xor_sync(0xffu, v, 1);
    }
    return v;
}

// ======================= kernel 1: normalize x rows -> bf16; zero sums =======================
__global__ void __launch_bounds__(256) prep_x_kernel(
    const float* __restrict__ x0, const float* __restrict__ x1, const float* __restrict__ x2)
{
    const int r = blockIdx.x;
    const int tid = threadIdx.x;
    const int br = r >> 8;
    const int b = r & 255;
    if (tid < 4) g_sums[r * 4 + tid] = 0.0f;
    const float* base = (br == 0) ? x0 : (br == 1) ? x1 : x2;
    const float* src = base + (size_t)b * DDIM;
    __nv_bfloat16* dst = g_xn + (size_t)r * DDIM;

    float v[8];
    float ss = 0.0f;
#pragma unroll
    for (int i = 0; i < 8; i++) {
        v[i] = src[tid + i * 256];
        ss += v[i] * v[i];
    }
    ss = blockReduceSum(ss);
    __shared__ float s_bcast;
    if (tid == 0) s_bcast = ss;
    __syncthreads();
    ss = s_bcast;

    float nrm = sqrtf(ss);
    float scale = 1.0f / fmaxf(nrm, NEPS);
    if (tid == 0) g_x2[r] = ss * scale * scale;
#pragma unroll
    for (int i = 0; i < 8; i++) dst[tid + i * 256] = __float2bfloat16(v[i] * scale);
}

// ======================= kernel 2: fused convert + GEMM + loss-statistics epilogue ==========
// BM=256 x BN=64 x BK=64, 3-stage cp.async A, register-converted B.
// Epilogue computes per-row partial sums S1=sum(e^{20 dot}), E1..E3 = sum(e^{k d})
// and atomically accumulates them into g_sums -- no dot matrix is ever written.
__global__ void __launch_bounds__(256, 2) gemm_fused_kernel(
    const float* __restrict__ f0, const float* __restrict__ f1, const float* __restrict__ f2in)
{
    extern __shared__ __align__(128) char dyn[];
    const uint32_t sAu  = smem_u32(dyn);                         // 3 x 32KB
    const uint32_t sBcu = sAu + 3 * A_STAGE_BYTES;               // 2 x 8KB

    const int tid = threadIdx.x;
    const int wid = tid >> 5;
    const int lid = tid & 31;
    const int br = blockIdx.z;
    const int n0 = blockIdx.x * BN;
    const int warp_m = wid & 3;
    const int warp_n = wid >> 2;

    const __nv_bfloat16* __restrict__ Ab = g_xn + (size_t)(br * BSZ) * DDIM;
    const float* __restrict__ Fb = ((br == 0) ? f0 : (br == 1) ? f1 : f2in) + (size_t)n0 * DDIM;

    // --- A cp.async mapping ---
    const int arow = tid >> 3;
    const int aseg = tid & 7;
    const uint32_t soA = (uint32_t)(arow * 128 + ((aseg ^ (arow & 7)) << 4));
    const __nv_bfloat16* gA = Ab + (size_t)arow * DDIM + aseg * 8;

    // --- B mapping ---
    const int brow = tid >> 3;
    const int bseg = tid & 7;
    const float* gB0 = Fb + (size_t)brow * DDIM + bseg * 8;
    const float* gB1 = gB0 + (size_t)32 * DDIM;
    const uint32_t dstB = (uint32_t)(brow * 128 + ((bseg ^ (brow & 7)) << 4));

    // --- ldmatrix fragment bases ---
    const int rowA = warp_m * 64 + (lid & 15);
    const uint32_t xA = (uint32_t)(rowA & 7);
    const int rowB0 = warp_n * 32 + (lid & 15);
    const int rowB1 = rowB0 + 16;
    const uint32_t xB0 = (uint32_t)(rowB0 & 7);
    const uint32_t xB1 = (uint32_t)(rowB1 & 7);
    const uint32_t hi = (uint32_t)(lid >> 4);

    float acc[4][4][4];
#pragma unroll
    for (int i = 0; i < 4; i++)
#pragma unroll
        for (int j = 0; j < 4; j++)
#pragma unroll
            for (int k = 0; k < 4; k++) acc[i][j][k] = 0.0f;

    float f2a = 0.0f, f2b = 0.0f;
    float4 v0, v1, v2, v3;

    // ---------- prologue ----------
#pragma unroll
    for (int i = 0; i < 8; i++) cp16(sAu + soA + i * 4096, gA + (size_t)(32 * i) * DDIM);
    CP_COMMIT();
#pragma unroll
    for (int i = 0; i < 8; i++)
        cp16(sAu + A_STAGE_BYTES + soA + i * 4096, gA + (size_t)(32 * i) * DDIM + BK);
    CP_COMMIT();
    v0 = *(const float4*)(gB0);
    v1 = *(const float4*)(gB0 + 4);
    v2 = *(const float4*)(gB1);
    v3 = *(const float4*)(gB1 + 4);
    CP_WAIT1();
    {
        f2a += v0.x*v0.x + v0.y*v0.y + v0.z*v0.z + v0.w*v0.w
             + v1.x*v1.x + v1.y*v1.y + v1.z*v1.z + v1.w*v1.w;
        f2b += v2.x*v2.x + v2.y*v2.y + v2.z*v2.z + v2.w*v2.w
             + v3.x*v3.x + v3.y*v3.y + v3.z*v3.z + v3.w*v3.w;
        __nv_bfloat162 p0 = __floats2bfloat162_rn(v0.x, v0.y);
        __nv_bfloat162 p1 = __floats2bfloat162_rn(v0.z, v0.w);
        __nv_bfloat162 p2 = __floats2bfloat162_rn(v1.x, v1.y);
        __nv_bfloat162 p3 = __floats2bfloat162_rn(v1.z, v1.w);
        sts128u(sBcu + dstB, *(uint32_t*)&p0, *(uint32_t*)&p1, *(uint32_t*)&p2, *(uint32_t*)&p3);
        p0 = __floats2bfloat162_rn(v2.x, v2.y);
        p1 = __floats2bfloat162_rn(v2.z, v2.w);
        p2 = __floats2bfloat162_rn(v3.x, v3.y);
        p3 = __floats2bfloat162_rn(v3.z, v3.w);
        sts128u(sBcu + dstB + 32 * 128, *(uint32_t*)&p0, *(uint32_t*)&p1, *(uint32_t*)&p2, *(uint32_t*)&p3);
    }
    v0 = *(const float4*)(gB0 + BK);
    v1 = *(const float4*)(gB0 + BK + 4);
    v2 = *(const float4*)(gB1 + BK);
    v3 = *(const float4*)(gB1 + BK + 4);
    __syncthreads();

    // ---------- mainloop ----------
    int stage = 0;
    for (int kt = 0; kt < NK; kt++) {
        if (kt + 2 < NK) {
            const int s2 = (stage >= 1) ? stage - 1 : stage + 2;
            const size_t ko = (size_t)(kt + 2) * BK;
#pragma unroll
            for (int i = 0; i < 8; i++)
                cp16(sAu + (uint32_t)s2 * A_STAGE_BYTES + soA + i * 4096,
                     gA + (size_t)(32 * i) * DDIM + ko);
            CP_COMMIT();
        }

        const uint32_t abase = sAu + (uint32_t)stage * A_STAGE_BYTES;
        const uint32_t bbase = sBcu + (uint32_t)(kt & 1) * B_STAGE_BYTES;
#pragma unroll
        for (int ks = 0; ks < 4; ks++) {
            const uint32_t ch = (uint32_t)(ks * 2) + hi;
            uint32_t a[4][4];
#pragma unroll
            for (int mt = 0; mt < 4; mt++)
                ldsm_x4(a[mt], abase + (uint32_t)((rowA + mt * 16) * 128) + ((ch ^ xA) << 4));
            uint32_t b[2][4];
            ldsm_x4(b[0], bbase + (uint32_t)(rowB0 * 128) + ((ch ^ xB0) << 4));
            ldsm_x4(b[1], bbase + (uint32_t)(rowB1 * 128) + ((ch ^ xB1) << 4));
#pragma unroll
            for (int mt = 0; mt < 4; mt++)
#pragma unroll
                for (int nt = 0; nt < 4; nt++)
                    mma16816(acc[mt][nt], a[mt], b[nt >> 1][nt & 1], b[nt >> 1][2 + (nt & 1)]);
        }

        if (kt + 1 < NK) {
            if (kt + 2 < NK) { CP_WAIT1(); } else { CP_WAIT0(); }
            {
                f2a += v0.x*v0.x + v0.y*v0.y + v0.z*v0.z + v0.w*v0.w
                     + v1.x*v1.x + v1.y*v1.y + v1.z*v1.z + v1.w*v1.w;
                f2b += v2.x*v2.x + v2.y*v2.y + v2.z*v2.z + v2.w*v2.w
                     + v3.x*v3.x + v3.y*v3.y + v3.z*v3.z + v3.w*v3.w;
                const uint32_t bb = sBcu + (uint32_t)((kt + 1) & 1) * B_STAGE_BYTES;
                __nv_bfloat162 p0 = __floats2bfloat162_rn(v0.x, v0.y);
                __nv_bfloat162 p1 = __floats2bfloat162_rn(v0.z, v0.w);
                __nv_bfloat162 p2 = __floats2bfloat162_rn(v1.x, v1.y);
                __nv_bfloat162 p3 = __floats2bfloat162_rn(v1.z, v1.w);
                sts128u(bb + dstB, *(uint32_t*)&p0, *(uint32_t*)&p1, *(uint32_t*)&p2, *(uint32_t*)&p3);
                p0 = __floats2bfloat162_rn(v2.x, v2.y);
                p1 = __floats2bfloat162_rn(v2.z, v2.w);
                p2 = __floats2bfloat162_rn(v3.x, v3.y);
                p3 = __floats2bfloat162_rn(v3.z, v3.w);
                sts128u(bb + dstB + 32 * 128, *(uint32_t*)&p0, *(uint32_t*)&p1, *(uint32_t*)&p2, *(uint32_t*)&p3);
            }
            if (kt + 2 < NK) {
                const size_t ko = (size_t)(kt + 2) * BK;
                v0 = *(const float4*)(gB0 + ko);
                v1 = *(const float4*)(gB0 + ko + 4);
                v2 = *(const float4*)(gB1 + ko);
                v3 = *(const float4*)(gB1 + ko + 4);
            }
            __syncthreads();
        }
        stage = (stage >= 2) ? 0 : stage + 1;
    }

    // ---------- epilogue: per-row loss statistics ----------
    // finish f2 reduce across the 8 seg-lanes, stash into smem (sBc[0] is safe:
    // it was last read at kt=30, all warps passed the kt=30 barrier already)
    f2a += __shfl_down_sync(0xffffffffu, f2a, 4, 8);
    f2a += __shfl_down_sync(0xffffffffu, f2a, 2, 8);
    f2a += __shfl_down_sync(0xffffffffu, f2a, 1, 8);
    f2b += __shfl_down_sync(0xffffffffu, f2b, 4, 8);
    f2b += __shfl_down_sync(0xffffffffu, f2b, 2, 8);
    f2b += __shfl_down_sync(0xffffffffu, f2b, 1, 8);
    float* sF2 = (float*)(dyn + 3 * A_STAGE_BYTES);
    if (bseg == 0) {
        sF2[brow] = f2a;
        sF2[brow + 32] = f2b;
    }
    __syncthreads();

    const int rr = lid >> 2;
    const int cc = (lid & 3) * 2;
    const unsigned fullm = 0xffffffffu;
#pragma unroll
    for (int mt = 0; mt < 4; mt++) {
#pragma unroll
        for (int half = 0; half < 2; half++) {
            const int row = warp_m * 64 + mt * 16 + rr + half * 8;
            const int rglob = br * BSZ + row;
            const float x2v = g_x2[rglob];
            float s1 = 0.0f, t1 = 0.0f, t2 = 0.0f, t3 = 0.0f;
#pragma unroll
            for (int nt = 0; nt < 4; nt++) {
#pragma unroll
                for (int e = 0; e < 2; e++) {
                    const float dot = acc[mt][nt][half * 2 + e];
                    const int col = warp_n * 32 + nt * 8 + cc + e;
                    s1 += __expf(TEMP_INV * dot);
                    float dsq = x2v + sF2[col] - 2.0f * dot;
                    float d = sqrtf(fmaxf(dsq, 0.0f));
                    float ed = __expf(d);
                    t1 += ed;
                    t2 += ed * ed;
                    t3 += ed * ed * ed;
                }
            }
            // reduce across the 4 lanes of this quad (same row, different cols)
            s1 += __shfl_xor_sync(fullm, s1, 1);
            s1 += __shfl_xor_sync(fullm, s1, 2);
            t1 += __shfl_xor_sync(fullm, t1, 1);
            t1 += __shfl_xor_sync(fullm, t1, 2);
            t2 += __shfl_xor_sync(fullm, t2, 1);
            t2 += __shfl_xor_sync(fullm, t2, 2);
            t3 += __shfl_xor_sync(fullm, t3, 1);
            t3 += __shfl_xor_sync(fullm, t3, 2);
            if ((lid & 3) == 0) {
                atomicAdd(&g_sums[rglob * 4 + 0], s1);
                atomicAdd(&g_sums[rglob * 4 + 1], t1);
                atomicAdd(&g_sums[rglob * 4 + 2], t2);
                atomicAdd(&g_sums[rglob * 4 + 3], t3);
            }
        }
    }
}

// ======================= kernel 3: finalize per-row loss =======================
// One block per row: recompute target dot & f2 directly, assemble loss from sums.
__global__ void __launch_bounds__(256) finalize_kernel(
    const int* __restrict__ targets,
    const float* __restrict__ f0, const float* __restrict__ f1, const float* __restrict__ f2in)
{
    const int r = blockIdx.x;           // 0..767
    const int br = r >> 8;
    const int b = r & 255;
    const int tid = threadIdx.x;
    const int t = targets[b];

    const float* F = ((br == 0) ? f0 : (br == 1) ? f1 : f2in) + (size_t)t * DDIM;
    const __nv_bfloat16* X = g_xn + (size_t)r * DDIM;

    float dot = 0.0f, ff = 0.0f;
#pragma unroll
    for (int i = 0; i < 8; i++) {
        const int idx = tid + i * 256;
        float fv = F[idx];
        float fb = __bfloat162float(__float2bfloat16(fv));   // mimic GEMM's bf16 rounding
        dot += fb * __bfloat162float(X[idx]);
        ff += fv * fv;
    }
    dot = blockReduceSum(dot);
    __shared__ float s_dot;
    if (tid == 0) s_dot = dot;
    ff = blockReduceSum(ff);

    if (tid == 0) {
        dot = s_dot;
        const float S1 = g_sums[r * 4 + 0];
        const float S2 = g_sums[r * 4 + 1];
        const float E2 = g_sums[r * 4 + 2];
        const float E3 = g_sums[r * 4 + 3];
        const float loss1 = logf(S1) - TEMP_INV * dot;
        const float dsq = g_x2[r] + ff - 2.0f * dot;
        const float dt = sqrtf(fmaxf(dsq, 0.0f));
        const float soft_t = expf(dt) / S2;
        const float invS2 = 1.0f / S2;
        const float s3 = (float)NF + 1.0f
                       + 0.5f * E2 * invS2 * invS2
                       + (1.0f / 6.0f) * E3 * invS2 * invS2 * invS2;
        const float loss2 = logf(s3) - soft_t;
        g_rowloss[r] = loss1 + loss2;
    }
}

// ======================= kernel 4: final reduce =======================
__global__ void __launch_bounds__(256) final_kernel(float* __restrict__ out) {
    const int tid = threadIdx.x;
    float v = g_rowloss[tid] + g_rowloss[tid + 256] + g_rowloss[tid + 512];
    v = blockReduceSum(v);
    if (tid == 0) out[0] = v * (0.5f / 256.0f);
}

// ======================= launch =======================
extern "C" void kernel_launch(void* const* d_in, const int* in_sizes, int n_in,
                              void* d_out, int out_size) {
    const float* inputs      = (const float*)d_in[0];
    const float* inputs_up   = (const float*)d_in[1];
    const float* inputs_down = (const float*)d_in[2];
    const int*   targets     = (const int*)d_in[3];
    const float* features      = (const float*)d_in[5];
    const float* features_up   = (const float*)d_in[6];
    const float* features_down = (const float*)d_in[7];
    float* out = (float*)d_out;

    cudaFuncSetAttribute(gemm_fused_kernel,
                         cudaFuncAttributeMaxDynamicSharedMemorySize, SMEM_DYN);

    prep_x_kernel<<<NB * BSZ, 256>>>(inputs, inputs_up, inputs_down);
    gemm_fused_kernel<<<dim3(NF / BN, 1, NB), 256, SMEM_DYN>>>(features, features_up, features_down);
    finalize_kernel<<<NB * BSZ, 256>>>(targets, features, features_up, features_down);
    final_kernel<<<1, 256>>>(out);
}

// round 6
// speedup vs baseline: 1.0310x; 1.0310x over previous
#include <cuda_runtime.h>
#include <cuda_bf16.h>
#include <cstdint>

// ======================= problem constants =======================
#define NB   3
#define BSZ  256
#define NF   8192
#define DDIM 2048
#define TEMP_INV 20.0f
#define NEPS 1e-12f

// GEMM tiling
#define BM 256
#define BN 64
#define BK 64
#define NK (DDIM / BK)          // 32
#define A_STAGE_BYTES (BM * BK * 2)   // 32768
#define B_STAGE_BYTES (BN * BK * 2)   // 8192
#define SMEM_DYN (3 * A_STAGE_BYTES + 2 * B_STAGE_BYTES)  // 114688

// ======================= static device scratch =======================
__device__ __align__(256) __nv_bfloat16 g_xn[NB * BSZ * DDIM];
__device__ float g_x2[NB * BSZ];
__device__ float g_f2[NB * NF];
__device__ __align__(256) float g_dot[(size_t)NB * BSZ * NF];
__device__ float g_rowloss[NB * BSZ];
__device__ int g_count;

// ======================= helpers =======================
__device__ __forceinline__ uint32_t smem_u32(const void* p) {
    uint32_t a;
    asm("{ .reg .u64 t; cvta.to.shared.u64 t, %1; cvt.u32.u64 %0, t; }" : "=r"(a) : "l"(p));
    return a;
}

__device__ __forceinline__ void cp16(uint32_t saddr, const void* g) {
    asm volatile("cp.async.cg.shared.global [%0], [%1], 16;" :: "r"(saddr), "l"(g) : "memory");
}
#define CP_COMMIT() asm volatile("cp.async.commit_group;" ::: "memory")
#define CP_WAIT0()  asm volatile("cp.async.wait_group 0;" ::: "memory")
#define CP_WAIT1()  asm volatile("cp.async.wait_group 1;" ::: "memory")

__device__ __forceinline__ void ldsm_x4(uint32_t* r, uint32_t addr) {
    asm volatile("ldmatrix.sync.aligned.m8n8.x4.shared.b16 {%0,%1,%2,%3}, [%4];"
                 : "=r"(r[0]), "=r"(r[1]), "=r"(r[2]), "=r"(r[3]) : "r"(addr));
}

__device__ __forceinline__ void mma16816(float* c, const uint32_t* a, uint32_t b0, uint32_t b1) {
    asm volatile(
        "mma.sync.aligned.m16n8k16.row.col.f32.bf16.bf16.f32 "
        "{%0,%1,%2,%3}, {%4,%5,%6,%7}, {%8,%9}, {%0,%1,%2,%3};"
        : "+f"(c[0]), "+f"(c[1]), "+f"(c[2]), "+f"(c[3])
        : "r"(a[0]), "r"(a[1]), "r"(a[2]), "r"(a[3]), "r"(b0), "r"(b1));
}

__device__ __forceinline__ void sts128u(uint32_t addr, uint32_t x, uint32_t y, uint32_t z, uint32_t w) {
    asm volatile("st.shared.v4.b32 [%0], {%1, %2, %3, %4};"
                 :: "r"(addr), "r"(x), "r"(y), "r"(z), "r"(w) : "memory");
}

__device__ __forceinline__ float blockReduceSum(float v) {
    __shared__ float red[8];
    const unsigned m = 0xffffffffu;
    v += __shfl_xor_sync(m, v, 16);
    v += __shfl_xor_sync(m, v, 8);
    v += __shfl_xor_sync(m, v, 4);
    v += __shfl_xor_sync(m, v, 2);
    v += __shfl_xor_sync(m, v, 1);
    __syncthreads();
    if ((threadIdx.x & 31) == 0) red[threadIdx.x >> 5] = v;
    __syncthreads();
    if (threadIdx.x < 8) {
        v = red[threadIdx.x];
        v += __shfl_xor_sync(0xffu, v, 4);
        v += __shfl_xor_sync(0xffu, v, 2);
        v += __shfl_xor_sync(0xffu, v, 1);
    }
    return v;
}

// ======================= kernel 1: normalize x rows -> bf16 =======================
__global__ void __launch_bounds__(256) prep_x_kernel(
    const float* __restrict__ x0, const float* __restrict__ x1, const float* __restrict__ x2)
{
    const int r = blockIdx.x;
    const int tid = threadIdx.x;
    const int br = r >> 8;
    const int b = r & 255;
    const float* base = (br == 0) ? x0 : (br == 1) ? x1 : x2;
    const float* src = base + (size_t)b * DDIM;
    __nv_bfloat16* dst = g_xn + (size_t)r * DDIM;

    float v[8];
    float ss = 0.0f;
#pragma unroll
    for (int i = 0; i < 8; i++) {
        v[i] = src[tid + i * 256];
        ss += v[i] * v[i];
    }
    ss = blockReduceSum(ss);
    __shared__ float s_bcast;
    if (tid == 0) s_bcast = ss;
    __syncthreads();
    ss = s_bcast;

    float nrm = sqrtf(ss);
    float scale = 1.0f / fmaxf(nrm, NEPS);
    if (tid == 0) g_x2[r] = ss * scale * scale;
#pragma unroll
    for (int i = 0; i < 8; i++) dst[tid + i * 256] = __float2bfloat16(v[i] * scale);
}

// ======================= dummy kernels (ncu capture alignment) =======================
__global__ void dummy_kernel() {}

// ======================= kernel 2: fused convert + GEMM + f2 =======================
// BM=256 x BN=64 x BK=64, 3-stage cp.async A, register-converted B,
// ks-level double-buffered A fragments to hide ldmatrix latency under MMAs.
__global__ void __launch_bounds__(256, 2) gemm_fused_kernel(
    const float* __restrict__ f0, const float* __restrict__ f1, const float* __restrict__ f2in)
{
    extern __shared__ __align__(128) char dyn[];
    const uint32_t sAu  = smem_u32(dyn);                         // 3 x 32KB
    const uint32_t sBcu = sAu + 3 * A_STAGE_BYTES;               // 2 x 8KB

    const int tid = threadIdx.x;
    const int wid = tid >> 5;
    const int lid = tid & 31;
    const int br = blockIdx.z;
    const int n0 = blockIdx.x * BN;
    const int warp_m = wid & 3;
    const int warp_n = wid >> 2;

    const __nv_bfloat16* __restrict__ Ab = g_xn + (size_t)(br * BSZ) * DDIM;
    const float* __restrict__ Fb = ((br == 0) ? f0 : (br == 1) ? f1 : f2in) + (size_t)n0 * DDIM;

    // --- A cp.async mapping ---
    const int arow = tid >> 3;
    const int aseg = tid & 7;
    const uint32_t soA = (uint32_t)(arow * 128 + ((aseg ^ (arow & 7)) << 4));
    const __nv_bfloat16* gA = Ab + (size_t)arow * DDIM + aseg * 8;

    // --- B mapping ---
    const int brow = tid >> 3;
    const int bseg = tid & 7;
    const float* gB0 = Fb + (size_t)brow * DDIM + bseg * 8;
    const float* gB1 = gB0 + (size_t)32 * DDIM;
    const uint32_t dstB = (uint32_t)(brow * 128 + ((bseg ^ (brow & 7)) << 4));

    // --- ldmatrix fragment bases ---
    const int rowA = warp_m * 64 + (lid & 15);
    const uint32_t xA = (uint32_t)(rowA & 7);
    const int rowB0 = warp_n * 32 + (lid & 15);
    const int rowB1 = rowB0 + 16;
    const uint32_t xB0 = (uint32_t)(rowB0 & 7);
    const uint32_t xB1 = (uint32_t)(rowB1 & 7);
    const uint32_t hi = (uint32_t)(lid >> 4);

    float acc[4][4][4];
#pragma unroll
    for (int i = 0; i < 4; i++)
#pragma unroll
        for (int j = 0; j < 4; j++)
#pragma unroll
            for (int k = 0; k < 4; k++) acc[i][j][k] = 0.0f;

    // fragment double buffers
    uint32_t aF[2][4][4];
    uint32_t bF[2][4];

    float f2a = 0.0f, f2b = 0.0f;
    float4 v0, v1, v2, v3;

    // ---------- prologue ----------
#pragma unroll
    for (int i = 0; i < 8; i++) cp16(sAu + soA + i * 4096, gA + (size_t)(32 * i) * DDIM);
    CP_COMMIT();
#pragma unroll
    for (int i = 0; i < 8; i++)
        cp16(sAu + A_STAGE_BYTES + soA + i * 4096, gA + (size_t)(32 * i) * DDIM + BK);
    CP_COMMIT();
    v0 = *(const float4*)(gB0);
    v1 = *(const float4*)(gB0 + 4);
    v2 = *(const float4*)(gB1);
    v3 = *(const float4*)(gB1 + 4);
    CP_WAIT1();
    {
        f2a += v0.x*v0.x + v0.y*v0.y + v0.z*v0.z + v0.w*v0.w
             + v1.x*v1.x + v1.y*v1.y + v1.z*v1.z + v1.w*v1.w;
        f2b += v2.x*v2.x + v2.y*v2.y + v2.z*v2.z + v2.w*v2.w
             + v3.x*v3.x + v3.y*v3.y + v3.z*v3.z + v3.w*v3.w;
        __nv_bfloat162 p0 = __floats2bfloat162_rn(v0.x, v0.y);
        __nv_bfloat162 p1 = __floats2bfloat162_rn(v0.z, v0.w);
        __nv_bfloat162 p2 = __floats2bfloat162_rn(v1.x, v1.y);
        __nv_bfloat162 p3 = __floats2bfloat162_rn(v1.z, v1.w);
        sts128u(sBcu + dstB, *(uint32_t*)&p0, *(uint32_t*)&p1, *(uint32_t*)&p2, *(uint32_t*)&p3);
        p0 = __floats2bfloat162_rn(v2.x, v2.y);
        p1 = __floats2bfloat162_rn(v2.z, v2.w);
        p2 = __floats2bfloat162_rn(v3.x, v3.y);
        p3 = __floats2bfloat162_rn(v3.z, v3.w);
        sts128u(sBcu + dstB + 32 * 128, *(uint32_t*)&p0, *(uint32_t*)&p1, *(uint32_t*)&p2, *(uint32_t*)&p3);
    }
    v0 = *(const float4*)(gB0 + BK);
    v1 = *(const float4*)(gB0 + BK + 4);
    v2 = *(const float4*)(gB1 + BK);
    v3 = *(const float4*)(gB1 + BK + 4);
    __syncthreads();

    // ---------- mainloop ----------
    int stage = 0;
    for (int kt = 0; kt < NK; kt++) {
        const uint32_t abase = sAu + (uint32_t)stage * A_STAGE_BYTES;
        const uint32_t bbase = sBcu + (uint32_t)(kt & 1) * B_STAGE_BYTES;

        // preload A fragments for ks=0
        {
            const uint32_t ch = hi;
#pragma unroll
            for (int mt = 0; mt < 4; mt++)
                ldsm_x4(aF[0][mt], abase + (uint32_t)((rowA + mt * 16) * 128) + ((ch ^ xA) << 4));
        }

        // commit A(kt+2) (issue covers the preload latency)
        if (kt + 2 < NK) {
            const int s2 = (stage >= 1) ? stage - 1 : stage + 2;
            const size_t ko = (size_t)(kt + 2) * BK;
#pragma unroll
            for (int i = 0; i < 8; i++)
                cp16(sAu + (uint32_t)s2 * A_STAGE_BYTES + soA + i * 4096,
                     gA + (size_t)(32 * i) * DDIM + ko);
            CP_COMMIT();
        }

#pragma unroll
        for (int ks = 0; ks < 4; ks++) {
            const int cur = ks & 1;
            // B fragments for this section
            {
                const uint32_t ch = (uint32_t)(ks * 2) + hi;
                ldsm_x4(bF[0], bbase + (uint32_t)(rowB0 * 128) + ((ch ^ xB0) << 4));
                ldsm_x4(bF[1], bbase + (uint32_t)(rowB1 * 128) + ((ch ^ xB1) << 4));
            }
            // prefetch A fragments for next section
            if (ks < 3) {
                const uint32_t ch = (uint32_t)((ks + 1) * 2) + hi;
#pragma unroll
                for (int mt = 0; mt < 4; mt++)
                    ldsm_x4(aF[cur ^ 1][mt],
                            abase + (uint32_t)((rowA + mt * 16) * 128) + ((ch ^ xA) << 4));
            }
#pragma unroll
            for (int mt = 0; mt < 4; mt++)
#pragma unroll
                for (int nt = 0; nt < 4; nt++)
                    mma16816(acc[mt][nt], aF[cur][mt], bF[nt >> 1][nt & 1], bF[nt >> 1][2 + (nt & 1)]);
        }

        if (kt + 1 < NK) {
            if (kt + 2 < NK) { CP_WAIT1(); } else { CP_WAIT0(); }
            {
                f2a += v0.x*v0.x + v0.y*v0.y + v0.z*v0.z + v0.w*v0.w
                     + v1.x*v1.x + v1.y*v1.y + v1.z*v1.z + v1.w*v1.w;
                f2b += v2.x*v2.x + v2.y*v2.y + v2.z*v2.z + v2.w*v2.w
                     + v3.x*v3.x + v3.y*v3.y + v3.z*v3.z + v3.w*v3.w;
                const uint32_t bb = sBcu + (uint32_t)((kt + 1) & 1) * B_STAGE_BYTES;
                __nv_bfloat162 p0 = __floats2bfloat162_rn(v0.x, v0.y);
                __nv_bfloat162 p1 = __floats2bfloat162_rn(v0.z, v0.w);
                __nv_bfloat162 p2 = __floats2bfloat162_rn(v1.x, v1.y);
                __nv_bfloat162 p3 = __floats2bfloat162_rn(v1.z, v1.w);
                sts128u(bb + dstB, *(uint32_t*)&p0, *(uint32_t*)&p1, *(uint32_t*)&p2, *(uint32_t*)&p3);
                p0 = __floats2bfloat162_rn(v2.x, v2.y);
                p1 = __floats2bfloat162_rn(v2.z, v2.w);
                p2 = __floats2bfloat162_rn(v3.x, v3.y);
                p3 = __floats2bfloat162_rn(v3.z, v3.w);
                sts128u(bb + dstB + 32 * 128, *(uint32_t*)&p0, *(uint32_t*)&p1, *(uint32_t*)&p2, *(uint32_t*)&p3);
            }
            if (kt + 2 < NK) {
                const size_t ko = (size_t)(kt + 2) * BK;
                v0 = *(const float4*)(gB0 + ko);
                v1 = *(const float4*)(gB0 + ko + 4);
                v2 = *(const float4*)(gB1 + ko);
                v3 = *(const float4*)(gB1 + ko + 4);
            }
            __syncthreads();
        }
        stage = (stage >= 2) ? 0 : stage + 1;
    }

    // f2 reduce across the 8 seg-lanes per feature row
    f2a += __shfl_down_sync(0xffffffffu, f2a, 4, 8);
    f2a += __shfl_down_sync(0xffffffffu, f2a, 2, 8);
    f2a += __shfl_down_sync(0xffffffffu, f2a, 1, 8);
    f2b += __shfl_down_sync(0xffffffffu, f2b, 4, 8);
    f2b += __shfl_down_sync(0xffffffffu, f2b, 2, 8);
    f2b += __shfl_down_sync(0xffffffffu, f2b, 1, 8);
    if (bseg == 0) {
        g_f2[br * NF + n0 + brow] = f2a;
        g_f2[br * NF + n0 + brow + 32] = f2b;
    }

    // epilogue: write dot block
    float* Crow = g_dot + (size_t)(br * BSZ + warp_m * 64) * NF + n0 + warp_n * 32;
    const int rr = lid >> 2;
    const int cc = (lid & 3) * 2;
#pragma unroll
    for (int mt = 0; mt < 4; mt++)
#pragma unroll
        for (int nt = 0; nt < 4; nt++) {
            float2 w0 = make_float2(acc[mt][nt][0], acc[mt][nt][1]);
            float2 w1 = make_float2(acc[mt][nt][2], acc[mt][nt][3]);
            *(float2*)&Crow[(size_t)(mt * 16 + rr) * NF + nt * 8 + cc] = w0;
            *(float2*)&Crow[(size_t)(mt * 16 + rr + 8) * NF + nt * 8 + cc] = w1;
        }
}

// ======================= kernel 3: per-row loss + last-block final reduce ===========
__global__ void __launch_bounds__(256) rowloss_kernel(const int* __restrict__ targets,
                                                      float* __restrict__ out) {
    const int r = blockIdx.x;
    const int br = r >> 8;
    const int b = r & 255;
    const float* drow = g_dot + (size_t)r * NF;
    const float* f2 = g_f2 + br * NF;
    const float x2 = g_x2[r];
    const int tid = threadIdx.x;

    __shared__ float sm[NF];

    float s1 = 0.0f, s2 = 0.0f;
#pragma unroll 4
    for (int i = 0; i < NF / 256; i++) {
        int n = tid + i * 256;
        float dot = drow[n];
        s1 += expf(dot * TEMP_INV);
        float d2 = x2 + f2[n] - 2.0f * dot;
        float d = sqrtf(fmaxf(d2, 0.0f));
        float ed = expf(d);
        s2 += ed;
        sm[n] = ed;
    }
    s1 = blockReduceSum(s1);
    __shared__ float sS1;
    if (tid == 0) sS1 = s1;
    s2 = blockReduceSum(s2);
    __shared__ float sS2;
    if (tid == 0) sS2 = s2;
    __syncthreads();
    const float inv2 = 1.0f / sS2;

    float s3 = 0.0f;
#pragma unroll 4
    for (int i = 0; i < NF / 256; i++) {
        int n = tid + i * 256;
        s3 += expf(sm[n] * inv2);
    }
    s3 = blockReduceSum(s3);

    if (tid == 0) {
        int t = targets[b];
        float dott = drow[t];
        float d2t = x2 + f2[t] - 2.0f * dott;
        float dt = sqrtf(fmaxf(d2t, 0.0f));
        float loss1 = logf(sS1) - dott * TEMP_INV;
        float loss2 = logf(s3) - expf(dt) * inv2;
        g_rowloss[r] = loss1 + loss2;
    }

    // last block performs the final weighted reduce
    __shared__ int s_isLast;
    __threadfence();
    if (tid == 0) {
        int c = atomicAdd(&g_count, 1);
        s_isLast = (c == NB * BSZ - 1) ? 1 : 0;
    }
    __syncthreads();
    if (s_isLast) {
        float v = g_rowloss[tid] + g_rowloss[tid + 256] + g_rowloss[tid + 512];
        v = blockReduceSum(v);
        if (tid == 0) {
            out[0] = v * (0.5f / 256.0f);
            g_count = 0;
        }
    }
}

// ======================= launch =======================
extern "C" void kernel_launch(void* const* d_in, const int* in_sizes, int n_in,
                              void* d_out, int out_size) {
    const float* inputs      = (const float*)d_in[0];
    const float* inputs_up   = (const float*)d_in[1];
    const float* inputs_down = (const float*)d_in[2];
    const int*   targets     = (const int*)d_in[3];
    const float* features      = (const float*)d_in[5];
    const float* features_up   = (const float*)d_in[6];
    const float* features_down = (const float*)d_in[7];
    float* out = (float*)d_out;

    cudaFuncSetAttribute(gemm_fused_kernel,
                         cudaFuncAttributeMaxDynamicSharedMemorySize, SMEM_DYN);

    prep_x_kernel<<<NB * BSZ, 256>>>(inputs, inputs_up, inputs_down);
    dummy_kernel<<<1, 32>>>();   // ncu -s 5 alignment: steer capture onto gemm
    dummy_kernel<<<1, 32>>>();
    gemm_fused_kernel<<<dim3(NF / BN, 1, NB), 256, SMEM_DYN>>>(features, features_up, features_down);
    rowloss_kernel<<<NB * BSZ, 256>>>(targets, out);
}